// round 2
// baseline (speedup 1.0000x reference)
#include <cuda_runtime.h>

#define HID   2048
#define NEXP  64
#define TOPK  8
#define TPB   64          // tokens per block
#define KC    64          // k-chunk
#define NCHUNK (HID/KC)   // 32
#define THREADS 256
#define PAD   68          // smem row stride (floats)
#define NTOK  16384
#define RS_H  0.022097086912079612f   // 1/sqrt(2048)
#define EPSV  1e-6f

__global__ void init_counts_kernel(float* __restrict__ out) {
    // zero the 64-float expert-count region at the tail of d_out
    out[2 * NTOK * TOPK + threadIdx.x] = 0.0f;
}

__global__ __launch_bounds__(THREADS, 2)
void gemma4_router_kernel(const float* __restrict__ hs,
                          const float* __restrict__ scale,
                          const float* __restrict__ pw,
                          const float* __restrict__ pes,
                          float* __restrict__ out) {
    __shared__ float xs[TPB][PAD];     // token tile (reused for logits in phase C)
    __shared__ float ws[NEXP][PAD];    // expert weight tile (scale-folded, XOR-swizzled)
    __shared__ float ssq_s[TPB];
    __shared__ float pes_s[NEXP];
    __shared__ int   hist_s[NEXP];

    const int tid  = threadIdx.x;
    const int tok0 = blockIdx.x * TPB;

    if (tid < NEXP) { pes_s[tid] = pes[tid]; hist_s[tid] = 0; }

    const int g  = tid >> 4;   // row group 0..15 (load mapping, also token group)
    const int c4 = tid & 15;   // float4 column 0..15 (load mapping, also expert group)

    // ---- software-pipelined load staging ----
    float4 xr[4], wr[4], sc;
    float  ssq[4] = {0.f, 0.f, 0.f, 0.f};

    {
        const float* hp = hs + (size_t)tok0 * HID + c4 * 4;
        const float* wp = pw + c4 * 4;
        #pragma unroll
        for (int i = 0; i < 4; i++) {
            int r = g + 16 * i;
            xr[i] = *(const float4*)(hp + (size_t)r * HID);
            wr[i] = *(const float4*)(wp + (size_t)r * HID);
        }
        sc = *(const float4*)(scale + c4 * 4);
    }

    // register tile: 4 tokens x 4 experts
    const int tt0 = g * 4;
    const int ee0 = c4 * 4;
    float acc[4][4];
    #pragma unroll
    for (int a = 0; a < 4; a++)
        #pragma unroll
        for (int b = 0; b < 4; b++) acc[a][b] = 0.f;

    for (int ch = 0; ch < NCHUNK; ch++) {
        // commit staged regs to smem (fold scale*H^-0.5 into W; accumulate sumsq)
        #pragma unroll
        for (int i = 0; i < 4; i++) {
            int r = g + 16 * i;
            *(float4*)&xs[r][c4 * 4] = xr[i];
            ssq[i] += xr[i].x * xr[i].x + xr[i].y * xr[i].y
                    + xr[i].z * xr[i].z + xr[i].w * xr[i].w;
            float4 wv;
            wv.x = wr[i].x * sc.x * RS_H;
            wv.y = wr[i].y * sc.y * RS_H;
            wv.z = wr[i].z * sc.z * RS_H;
            wv.w = wr[i].w * sc.w * RS_H;
            int col = (c4 * 4) ^ (((r >> 2) & 15) << 2);   // XOR swizzle, 16B granular
            *(float4*)&ws[r][col] = wv;
        }
        __syncthreads();

        // prefetch next chunk into registers (overlaps with the FMA loop below)
        if (ch + 1 < NCHUNK) {
            const float* hpn = hs + (size_t)tok0 * HID + (ch + 1) * KC + c4 * 4;
            const float* wpn = pw + (ch + 1) * KC + c4 * 4;
            #pragma unroll
            for (int i = 0; i < 4; i++) {
                int r = g + 16 * i;
                xr[i] = *(const float4*)(hpn + (size_t)r * HID);
                wr[i] = *(const float4*)(wpn + (size_t)r * HID);
            }
            sc = *(const float4*)(scale + (ch + 1) * KC + c4 * 4);
        }

        // GEMM on the chunk: 16 k-steps x (8 LDS.128 + 64 FFMA)
        #pragma unroll
        for (int k = 0; k < KC; k += 4) {
            float4 xv[4], wv[4];
            #pragma unroll
            for (int a = 0; a < 4; a++)
                xv[a] = *(const float4*)&xs[tt0 + a][k];
            #pragma unroll
            for (int b = 0; b < 4; b++) {
                int e = ee0 + b;
                wv[b] = *(const float4*)&ws[e][k ^ (((e >> 2) & 15) << 2)];
            }
            #pragma unroll
            for (int a = 0; a < 4; a++)
                #pragma unroll
                for (int b = 0; b < 4; b++)
                    acc[a][b] += xv[a].x * wv[b].x + xv[a].y * wv[b].y
                               + xv[a].z * wv[b].z + xv[a].w * wv[b].w;
        }
        __syncthreads();
    }

    // ---- per-token sum-of-squares reduction (16 threads share each row) ----
    #pragma unroll
    for (int i = 0; i < 4; i++) {
        float v = ssq[i];
        v += __shfl_xor_sync(0xffffffffu, v, 1);
        v += __shfl_xor_sync(0xffffffffu, v, 2);
        v += __shfl_xor_sync(0xffffffffu, v, 4);
        v += __shfl_xor_sync(0xffffffffu, v, 8);
        if (c4 == 0) ssq_s[g + 16 * i] = v;
    }
    __syncthreads();

    // ---- apply RMS factor, write logits into xs (reuse) ----
    float f[4];
    #pragma unroll
    for (int a = 0; a < 4; a++)
        f[a] = rsqrtf(ssq_s[tt0 + a] * (1.0f / HID) + EPSV);
    __syncthreads();
    #pragma unroll
    for (int a = 0; a < 4; a++)
        #pragma unroll
        for (int b = 0; b < 4; b++)
            xs[tt0 + a][ee0 + b] = acc[a][b] * f[a];
    __syncthreads();

    // ---- phase C: softmax + top-8 (one warp handles 8 tokens) ----
    const int wid = tid >> 5, lane = tid & 31;
    for (int t = wid * 8; t < wid * 8 + 8; t++) {
        float v0 = xs[t][lane];
        float v1 = xs[t][lane + 32];

        float m = fmaxf(v0, v1);
        #pragma unroll
        for (int s = 16; s > 0; s >>= 1)
            m = fmaxf(m, __shfl_xor_sync(0xffffffffu, m, s));

        float p0 = expf(v0 - m);
        float p1 = expf(v1 - m);
        float sum = p0 + p1;
        #pragma unroll
        for (int s = 16; s > 0; s >>= 1)
            sum += __shfl_xor_sync(0xffffffffu, sum, s);
        float inv = 1.0f / sum;
        p0 *= inv; p1 *= inv;

        float wsum = 0.f;
        float myv = 0.f; int myi = 0;
        #pragma unroll
        for (int r = 0; r < TOPK; r++) {
            // lane-local best, tie -> lower index
            float bv = p0; int bi = lane;
            if (p1 > bv) { bv = p1; bi = lane + 32; }
            #pragma unroll
            for (int s = 16; s > 0; s >>= 1) {
                float ov = __shfl_xor_sync(0xffffffffu, bv, s);
                int   oi = __shfl_xor_sync(0xffffffffu, bi, s);
                if (ov > bv || (ov == bv && oi < bi)) { bv = ov; bi = oi; }
            }
            wsum += bv;
            if (lane == r) { myv = bv; myi = bi; }
            if (bi == lane)            p0 = -1.f;
            else if (bi == lane + 32)  p1 = -1.f;
        }

        if (lane < TOPK) {
            int gt = tok0 + t;
            out[(size_t)gt * TOPK + lane] = myv / wsum * pes_s[myi];
            out[(size_t)NTOK * TOPK + (size_t)gt * TOPK + lane] = (float)myi;
            atomicAdd(&hist_s[myi], 1);
        }
    }

    __syncthreads();
    if (tid < NEXP)
        atomicAdd(&out[2 * NTOK * TOPK + tid], (float)hist_s[tid]);
}

extern "C" void kernel_launch(void* const* d_in, const int* in_sizes, int n_in,
                              void* d_out, int out_size) {
    const float* hs    = (const float*)d_in[0];   // [4,4096,2048] f32
    const float* scale = (const float*)d_in[1];   // [2048] f32
    const float* pw    = (const float*)d_in[2];   // [64,2048] f32
    const float* pes   = (const float*)d_in[3];   // [64] f32
    float* out = (float*)d_out;                   // weights | indices | counts

    init_counts_kernel<<<1, NEXP>>>(out);
    gemma4_router_kernel<<<NTOK / TPB, THREADS>>>(hs, scale, pw, pes, out);
}